// round 14
// baseline (speedup 1.0000x reference)
#include <cuda_runtime.h>
#include <cuda_fp16.h>
#include <stdint.h>

// ScaledDotProductAttention: B=2, H=16, S=2048, D=64, scale=8
#define BB 2
#define HH 16
#define SS 2048
#define DD 64
#define QB 64              // q rows per CTA
#define NCA 128            // k cols per A chunk
#define NCHA (SS / NCA)    // 16
#define NCBI 128           // k cols per B iteration (2 x 64 sub-chunks)
#define NCHBI (SS / NCBI)  // 16
#define NTHR 256           // 8 warps: 4 q-groups x 2 col-halves
#define NELEM (BB * HH * SS * DD)

#define STRB 144                 // smem row stride bytes (ldmatrix conflict-free)
#define TILE64 (64 * STRB)       // 9216
#define TILE128 (128 * STRB)     // 18432

#define OFF_QH 0
#define OFF_QL TILE64
#define OFF_STAGE (2 * TILE64)
// stage st: [KH(128 rows) | VH(128 rows)] ; A uses KH slot only
#define STK_OFF(st) (OFF_STAGE + (st) * 2 * TILE128)
#define STV_OFF(st) (STK_OFF(st) + TILE128)
#define OFF_OST OFF_STAGE                       // O fp32 stage overlays stages at end
#define OFF_MSKI (OFF_STAGE + 4 * TILE128)      // int[2048] (transient)
#define OFF_MSKH (OFF_MSKI + SS * 4)            // half2 bias[1024]
#define OFF_L2   (OFF_MSKH + SS * 2)            // float[64][2]
#define SMEM_TOTAL (OFF_L2 + 64 * 2 * 4)        // 104960 B -> 2 CTAs/SM

// pre-converted fp16 tensors (Q pre-scaled by log2(e)/8); K,V single-term, Q hi/lo
__device__ __half g_qh[NELEM], g_ql[NELEM];
__device__ __half g_kh[NELEM];
__device__ __half g_vh[NELEM];

__device__ __forceinline__ uint32_t s2u(const void* p) {
    uint32_t a;
    asm("{ .reg .u64 t; cvta.to.shared.u64 t, %1; cvt.u32.u64 %0, t; }" : "=r"(a) : "l"(p));
    return a;
}
__device__ __forceinline__ void ldsm4(uint32_t r[4], uint32_t a) {
    asm volatile("ldmatrix.sync.aligned.m8n8.x4.shared.b16 {%0,%1,%2,%3}, [%4];"
                 : "=r"(r[0]), "=r"(r[1]), "=r"(r[2]), "=r"(r[3]) : "r"(a));
}
__device__ __forceinline__ void ldsm4t(uint32_t r[4], uint32_t a) {
    asm volatile("ldmatrix.sync.aligned.m8n8.x4.trans.shared.b16 {%0,%1,%2,%3}, [%4];"
                 : "=r"(r[0]), "=r"(r[1]), "=r"(r[2]), "=r"(r[3]) : "r"(a));
}
__device__ __forceinline__ void mmah(float c[4], const uint32_t a[4], uint32_t b0, uint32_t b1) {
    asm volatile("mma.sync.aligned.m16n8k16.row.col.f32.f16.f16.f32 "
                 "{%0,%1,%2,%3}, {%4,%5,%6,%7}, {%8,%9}, {%0,%1,%2,%3};"
                 : "+f"(c[0]), "+f"(c[1]), "+f"(c[2]), "+f"(c[3])
                 : "r"(a[0]), "r"(a[1]), "r"(a[2]), "r"(a[3]), "r"(b0), "r"(b1));
}
__device__ __forceinline__ uint32_t pkh(float a, float b) {
    __half2 t = __floats2half2_rn(a, b);
    return *(uint32_t*)&t;
}
// f16x2 exp2 (one MUFU op for two elements)
__device__ __forceinline__ __half2 h2ex2(__half2 x) {
    uint32_t xi = *(uint32_t*)&x, r;
    asm("ex2.approx.f16x2 %0, %1;" : "=r"(r) : "r"(xi));
    return *(__half2*)&r;
}
#define CPA16(dst, src) \
    asm volatile("cp.async.cg.shared.global [%0], [%1], 16;" :: "r"(dst), "l"(src) : "memory")
#define CPA_COMMIT() asm volatile("cp.async.commit_group;" ::: "memory")
#define CPA_WAIT0()  asm volatile("cp.async.wait_group 0;" ::: "memory")

// ---- pre-pass: Q -> fp16 hi/lo (scaled), K/V -> fp16 ----
__global__ void convert_kernel(const float* __restrict__ Q, const float* __restrict__ K,
                               const float* __restrict__ V)
{
    long i = (long)blockIdx.x * blockDim.x + threadIdx.x;
    if (i >= NELEM / 4) return;
    long e = i * 4;
    const float QSC = 0.125f * 1.4426950408889634f;   // (1/8)*log2(e): exp -> exp2
    float4 q = *(const float4*)&Q[e];
    q.x *= QSC; q.y *= QSC; q.z *= QSC; q.w *= QSC;
    float h0 = __half2float(__float2half_rn(q.x));
    float h1 = __half2float(__float2half_rn(q.y));
    float h2 = __half2float(__float2half_rn(q.z));
    float h3 = __half2float(__float2half_rn(q.w));
    *(uint2*)&g_qh[e] = make_uint2(pkh(h0, h1), pkh(h2, h3));
    *(uint2*)&g_ql[e] = make_uint2(pkh(q.x - h0, q.y - h1), pkh(q.z - h2, q.w - h3));
    float4 k = *(const float4*)&K[e];
    *(uint2*)&g_kh[e] = make_uint2(pkh(k.x, k.y), pkh(k.z, k.w));
    float4 v = *(const float4*)&V[e];
    *(uint2*)&g_vh[e] = make_uint2(pkh(v.x, v.y), pkh(v.z, v.w));
}

// cp.async [rows x 64] fp16 tile into stride-144 smem
__device__ __forceinline__ void cpa_tile64(uint32_t dstbase, const __half* src, int tid) {
    #pragma unroll
    for (int i = tid; i < 512; i += NTHR) {
        int r = i >> 3, c8 = i & 7;
        CPA16(dstbase + r * STRB + c8 * 16, src + (long)r * DD + c8 * 8);
    }
}
__device__ __forceinline__ void cpa_tile128(uint32_t dstbase, const __half* src, int tid) {
    #pragma unroll
    for (int i = tid; i < 1024; i += NTHR) {
        int r = i >> 3, c8 = i & 7;
        CPA16(dstbase + r * STRB + c8 * 16, src + (long)r * DD + c8 * 8);
    }
}

__global__ __launch_bounds__(NTHR, 2)
void fa_mma_kernel(const int* __restrict__ mask,
                   float* __restrict__ out_o, float* __restrict__ out_p)
{
    extern __shared__ char sm[];
    const uint32_t sb = s2u(sm);
    const int tid = threadIdx.x, wid = tid >> 5, lane = tid & 31;
    const int qg = wid & 3, cg = wid >> 2;
    const int q0 = qg * 16;

    const int qtile = blockIdx.x, h = blockIdx.y, b = blockIdx.z;
    const long bh = (long)(b * HH + h);
    const long qbase = bh * SS + (long)qtile * QB;
    const long kvbase = bh * SS;

    // ---- prologue: Q tiles + mask + A chunk 0 (128-row KH) ----
    cpa_tile64(sb + OFF_QH, g_qh + qbase * DD, tid);
    cpa_tile64(sb + OFF_QL, g_ql + qbase * DD, tid);
    #pragma unroll
    for (int i = tid; i < 512; i += NTHR)
        CPA16(sb + OFF_MSKI + i * 16, mask + (long)b * SS + i * 4);
    cpa_tile128(sb + STK_OFF(0), g_kh + kvbase * DD, tid);
    CPA_COMMIT();

    // per-lane ldmatrix addresses
    const uint32_t aoff = (uint32_t)(q0 + (lane & 15)) * STRB + ((lane >> 4) & 1) * 16;
    const uint32_t koffA = (uint32_t)(cg * 64 + (lane & 7) + ((lane & 16) ? 8 : 0)) * STRB
                         + ((lane & 8) ? 16 : 0);
    const uint32_t koffB = (uint32_t)(cg * 32 + (lane & 7) + ((lane & 16) ? 8 : 0)) * STRB
                         + ((lane & 8) ? 16 : 0);
    const uint32_t voffB = (uint32_t)(cg * 32 + (lane & 15)) * STRB + ((lane >> 4) & 1) * 16;

    __half2* fbh = (__half2*)(sm + OFF_MSKH);

    CPA_WAIT0();
    __syncthreads();

    // mask ints -> half2 bias (0 pass, -inf masked)
    {
        const int2* mi = (const int2*)(sm + OFF_MSKI);
        for (int i = tid; i < SS / 2; i += NTHR) {
            int2 m = mi[i];
            fbh[i] = __floats2half2_rn(m.x ? 0.0f : -1e30f, m.y ? 0.0f : -1e30f);
        }
    }
    // hoist Q fragments (m16 x k64, hi+lo = 32 regs)
    uint32_t aHq[4][4], aLq[4][4];
    #pragma unroll
    for (int s = 0; s < 4; s++) {
        ldsm4(aHq[s], sb + OFF_QH + aoff + s * 32);
        ldsm4(aLq[s], sb + OFF_QL + aoff + s * 32);
    }
    __syncthreads();   // bias visible to all

    // ========= Pass A: 1-term fp16 scores -> row sums (f16x2 exp path) =========
    float rs0 = 0.0f, rs1 = 0.0f;
    for (int ch = 0; ch < NCHA; ch++) {
        const int st = ch & 1;
        if (ch > 0) { CPA_WAIT0(); __syncthreads(); }
        if (ch + 1 < NCHA) {
            cpa_tile128(sb + STK_OFF(st ^ 1),
                        g_kh + (kvbase + (long)(ch + 1) * NCA) * DD, tid);
            CPA_COMMIT();
        }

        float acc[8][4];
        #pragma unroll
        for (int j = 0; j < 8; j++)
            #pragma unroll
            for (int i = 0; i < 4; i++) acc[j][i] = 0.0f;
        #pragma unroll
        for (int s = 0; s < 4; s++) {
            #pragma unroll
            for (int jp = 0; jp < 4; jp++) {
                uint32_t bH[4];
                ldsm4(bH, sb + STK_OFF(st) + koffA + jp * (16 * STRB) + s * 32);
                mmah(acc[2 * jp],     aHq[s], bH[0], bH[1]);
                mmah(acc[2 * jp + 1], aHq[s], bH[2], bH[3]);
            }
        }
        __half2 hs0 = __floats2half2_rn(0.f, 0.f), hs1 = hs0;
        #pragma unroll
        for (int jt = 0; jt < 8; jt++) {
            int colb = ch * NCA + cg * 64 + 8 * jt + 2 * (lane & 3);
            __half2 fb = fbh[colb >> 1];
            hs0 = __hadd2(hs0, h2ex2(__hadd2(__floats2half2_rn(acc[jt][0], acc[jt][1]), fb)));
            hs1 = __hadd2(hs1, h2ex2(__hadd2(__floats2half2_rn(acc[jt][2], acc[jt][3]), fb)));
        }
        rs0 += __low2float(hs0) + __high2float(hs0);
        rs1 += __low2float(hs1) + __high2float(hs1);
    }

    __syncthreads();   // all warps done with A stages

    // prefetch pass-B chunk 0 (KH128, VH128) — overlaps rowsum reduction
    cpa_tile128(sb + STK_OFF(0), g_kh + kvbase * DD, tid);
    cpa_tile128(sb + STV_OFF(0), g_vh + kvbase * DD, tid);
    CPA_COMMIT();

    // ---- row sums: quad-lane reduce, cross-half via smem ----
    rs0 += __shfl_xor_sync(0xffffffffu, rs0, 1);
    rs0 += __shfl_xor_sync(0xffffffffu, rs0, 2);
    rs1 += __shfl_xor_sync(0xffffffffu, rs1, 1);
    rs1 += __shfl_xor_sync(0xffffffffu, rs1, 2);
    float* l2p = (float*)(sm + OFF_L2);
    if ((lane & 3) == 0) {
        l2p[2 * (q0 + (lane >> 2)) + cg]     = rs0;
        l2p[2 * (q0 + 8 + (lane >> 2)) + cg] = rs1;
    }
    __syncthreads();
    const float il0 = 1.0f / (l2p[2 * (q0 + (lane >> 2))] + l2p[2 * (q0 + (lane >> 2)) + 1]);
    const float il1 = 1.0f / (l2p[2 * (q0 + 8 + (lane >> 2))] + l2p[2 * (q0 + 8 + (lane >> 2)) + 1]);
    const long row0 = qbase + q0 + (lane >> 2);

    float oacc[8][4];
    #pragma unroll
    for (int j = 0; j < 8; j++)
        #pragma unroll
        for (int i = 0; i < 4; i++) oacc[j][i] = 0.0f;

    // ===== Pass B: 2-term S -> f16x2 exp -> probs out + PV; 2 sub-chunks/iter =====
    for (int ch = 0; ch < NCHBI; ch++) {
        const int st = ch & 1;
        CPA_WAIT0();
        __syncthreads();
        if (ch + 1 < NCHBI) {
            const long nb = (kvbase + (long)(ch + 1) * NCBI) * DD;
            const int ns = st ^ 1;
            cpa_tile128(sb + STK_OFF(ns), g_kh + nb, tid);
            cpa_tile128(sb + STV_OFF(ns), g_vh + nb, tid);
            CPA_COMMIT();
        }

        #pragma unroll
        for (int sc = 0; sc < 2; sc++) {
            const uint32_t kof = sb + STK_OFF(st) + (uint32_t)(sc * 64) * STRB + koffB;
            const uint32_t vof = sb + STV_OFF(st) + (uint32_t)(sc * 64) * STRB + voffB;

            // 2-term S over warp's n32
            float acc[4][4];
            #pragma unroll
            for (int j = 0; j < 4; j++)
                #pragma unroll
                for (int i = 0; i < 4; i++) acc[j][i] = 0.0f;
            #pragma unroll
            for (int s = 0; s < 4; s++) {
                #pragma unroll
                for (int jp = 0; jp < 2; jp++) {
                    uint32_t bH[4];
                    ldsm4(bH, kof + jp * (16 * STRB) + s * 32);
                    mmah(acc[2 * jp],     aHq[s], bH[0], bH[1]);
                    mmah(acc[2 * jp + 1], aHq[s], bH[2], bH[3]);
                    mmah(acc[2 * jp],     aLq[s], bH[0], bH[1]);
                    mmah(acc[2 * jp + 1], aLq[s], bH[2], bH[3]);
                }
            }

            #pragma unroll
            for (int s2 = 0; s2 < 2; s2++) {
                uint32_t PH[4];
                #pragma unroll
                for (int hf = 0; hf < 2; hf++) {
                    const int jt = 2 * s2 + hf;
                    int colb = ch * NCBI + sc * 64 + cg * 32 + 8 * jt + 2 * (lane & 3);
                    __half2 fb = fbh[colb >> 1];
                    __half2 p01 = h2ex2(__hadd2(__floats2half2_rn(acc[jt][0], acc[jt][1]), fb));
                    __half2 p23 = h2ex2(__hadd2(__floats2half2_rn(acc[jt][2], acc[jt][3]), fb));
                    // normalized probs out (fp16-rounded values * il)
                    *(float2*)&out_p[row0 * SS + colb] =
                        make_float2(__low2float(p01) * il0, __high2float(p01) * il0);
                    *(float2*)&out_p[(row0 + 8) * SS + colb] =
                        make_float2(__low2float(p23) * il1, __high2float(p23) * il1);
                    PH[2 * hf]     = *(uint32_t*)&p01;
                    PH[2 * hf + 1] = *(uint32_t*)&p23;
                }
                #pragma unroll
                for (int dp = 0; dp < 4; dp++) {
                    uint32_t vH[4];
                    ldsm4t(vH, vof + s2 * (16 * STRB) + dp * 32);
                    mmah(oacc[2 * dp],     PH, vH[0], vH[1]);
                    mmah(oacc[2 * dp + 1], PH, vH[2], vH[3]);
                }
            }
        }
    }

    __syncthreads();   // all pass-B compute done (stage region free for staging)

    // ---- O cross-half reduction, normalize at write ----
    float* stg = (float*)(sm + OFF_OST);
    const int rlo = q0 + (lane >> 2), rhi = rlo + 8;
    if (cg == 1) {
        #pragma unroll
        for (int nt = 0; nt < 8; nt++) {
            int c = 8 * nt + 2 * (lane & 3);
            *(float2*)&stg[rlo * 64 + c] = make_float2(oacc[nt][0], oacc[nt][1]);
            *(float2*)&stg[rhi * 64 + c] = make_float2(oacc[nt][2], oacc[nt][3]);
        }
    }
    __syncthreads();
    if (cg == 0) {
        #pragma unroll
        for (int nt = 0; nt < 8; nt++) {
            int c = 8 * nt + 2 * (lane & 3);
            float2 s0 = *(const float2*)&stg[rlo * 64 + c];
            float2 s1 = *(const float2*)&stg[rhi * 64 + c];
            *(float2*)&out_o[row0 * DD + c] =
                make_float2((oacc[nt][0] + s0.x) * il0, (oacc[nt][1] + s0.y) * il0);
            *(float2*)&out_o[(row0 + 8) * DD + c] =
                make_float2((oacc[nt][2] + s1.x) * il1, (oacc[nt][3] + s1.y) * il1);
        }
    }
}

extern "C" void kernel_launch(void* const* d_in, const int* in_sizes, int n_in,
                              void* d_out, int out_size)
{
    const float* Q    = (const float*)d_in[0];
    const float* K    = (const float*)d_in[1];
    const float* V    = (const float*)d_in[2];
    const int*   mask = (const int*)d_in[3];

    float* out_o = (float*)d_out;                       // [B,H,S,D]
    float* out_p = out_o + (size_t)BB * HH * SS * DD;   // [B,H,S,S]

    convert_kernel<<<NELEM / 4 / 256, 256>>>(Q, K, V);

    cudaFuncSetAttribute(fa_mma_kernel,
                         cudaFuncAttributeMaxDynamicSharedMemorySize, SMEM_TOTAL);
    dim3 grid(SS / QB, HH, BB);   // (32, 16, 2) = 1024 CTAs, 2 per SM
    fa_mma_kernel<<<grid, NTHR, SMEM_TOTAL>>>(mask, out_o, out_p);
}

// round 15
// speedup vs baseline: 1.1269x; 1.1269x over previous
#include <cuda_runtime.h>
#include <cuda_fp16.h>
#include <stdint.h>

// ScaledDotProductAttention: B=2, H=16, S=2048, D=64, scale=8
#define BB 2
#define HH 16
#define SS 2048
#define DD 64
#define QB 64              // q rows per CTA
#define NCB 64             // k cols per B chunk
#define NCHB (SS / NCB)    // 32
#define NCA 128            // k cols per A chunk
#define NCHA (SS / NCA)    // 16
#define NTHR 256           // 8 warps: 4 q-groups x 2 col-halves
#define NELEM (BB * HH * SS * DD)

#define STRB 144                 // smem row stride bytes (ldmatrix conflict-free)
#define TILE64 (64 * STRB)       // 9216

#define OFF_QH 0
#define OFF_STAGE TILE64
// B stages: st{0,1} x {KH,VH}. A stages: st*2*TILE64 (128-row KH each).
#define STB_OFF(st, t) (OFF_STAGE + ((st) * 2 + (t)) * TILE64)
#define STA_OFF(st)    (OFF_STAGE + (st) * 2 * TILE64)
#define OFF_OST OFF_STAGE                     // O fp32 stage (16KB) overlays stages
#define OFF_MSKF (OFF_STAGE + 4 * TILE64)     // float bias[2048] (ints staged here)
#define OFF_MSKH (OFF_MSKF + SS * 4)          // half2 bias[1024]
#define OFF_L2   (OFF_MSKH + SS * 2)          // float[64][2]
#define SMEM_TOTAL (OFF_L2 + 64 * 2 * 4)      // 58880 B -> 2 CTAs/SM

// pre-converted fp16 tensors (Q pre-scaled by log2(e)/8); all single-term
__device__ __half g_qh[NELEM];
__device__ __half g_kh[NELEM];
__device__ __half g_vh[NELEM];

__device__ __forceinline__ uint32_t s2u(const void* p) {
    uint32_t a;
    asm("{ .reg .u64 t; cvta.to.shared.u64 t, %1; cvt.u32.u64 %0, t; }" : "=r"(a) : "l"(p));
    return a;
}
__device__ __forceinline__ void ldsm4(uint32_t r[4], uint32_t a) {
    asm volatile("ldmatrix.sync.aligned.m8n8.x4.shared.b16 {%0,%1,%2,%3}, [%4];"
                 : "=r"(r[0]), "=r"(r[1]), "=r"(r[2]), "=r"(r[3]) : "r"(a));
}
__device__ __forceinline__ void ldsm4t(uint32_t r[4], uint32_t a) {
    asm volatile("ldmatrix.sync.aligned.m8n8.x4.trans.shared.b16 {%0,%1,%2,%3}, [%4];"
                 : "=r"(r[0]), "=r"(r[1]), "=r"(r[2]), "=r"(r[3]) : "r"(a));
}
__device__ __forceinline__ void mmah(float c[4], const uint32_t a[4], uint32_t b0, uint32_t b1) {
    asm volatile("mma.sync.aligned.m16n8k16.row.col.f32.f16.f16.f32 "
                 "{%0,%1,%2,%3}, {%4,%5,%6,%7}, {%8,%9}, {%0,%1,%2,%3};"
                 : "+f"(c[0]), "+f"(c[1]), "+f"(c[2]), "+f"(c[3])
                 : "r"(a[0]), "r"(a[1]), "r"(a[2]), "r"(a[3]), "r"(b0), "r"(b1));
}
// f16-accumulator mma (2x rate on legacy HMMA paths)
__device__ __forceinline__ void mmah16(uint32_t c[2], const uint32_t a[4], uint32_t b0, uint32_t b1) {
    asm volatile("mma.sync.aligned.m16n8k16.row.col.f16.f16.f16.f16 "
                 "{%0,%1}, {%2,%3,%4,%5}, {%6,%7}, {%0,%1};"
                 : "+r"(c[0]), "+r"(c[1])
                 : "r"(a[0]), "r"(a[1]), "r"(a[2]), "r"(a[3]), "r"(b0), "r"(b1));
}
__device__ __forceinline__ uint32_t pkh(float a, float b) {
    __half2 t = __floats2half2_rn(a, b);
    return *(uint32_t*)&t;
}
__device__ __forceinline__ float ex2f(float x) {
    float r;
    asm("ex2.approx.f32 %0, %1;" : "=f"(r) : "f"(x));
    return r;
}
__device__ __forceinline__ __half2 h2ex2(__half2 x) {
    uint32_t xi = *(uint32_t*)&x, r;
    asm("ex2.approx.f16x2 %0, %1;" : "=r"(r) : "r"(xi));
    return *(__half2*)&r;
}
#define CPA16(dst, src) \
    asm volatile("cp.async.cg.shared.global [%0], [%1], 16;" :: "r"(dst), "l"(src) : "memory")
#define CPA_COMMIT() asm volatile("cp.async.commit_group;" ::: "memory")
#define CPA_WAIT0()  asm volatile("cp.async.wait_group 0;" ::: "memory")

// ---- pre-pass: Q (scaled), K, V -> fp16 ----
__global__ void convert_kernel(const float* __restrict__ Q, const float* __restrict__ K,
                               const float* __restrict__ V)
{
    long i = (long)blockIdx.x * blockDim.x + threadIdx.x;
    if (i >= NELEM / 4) return;
    long e = i * 4;
    const float QSC = 0.125f * 1.4426950408889634f;   // (1/8)*log2(e): exp -> exp2
    float4 q = *(const float4*)&Q[e];
    *(uint2*)&g_qh[e] = make_uint2(pkh(q.x * QSC, q.y * QSC), pkh(q.z * QSC, q.w * QSC));
    float4 k = *(const float4*)&K[e];
    *(uint2*)&g_kh[e] = make_uint2(pkh(k.x, k.y), pkh(k.z, k.w));
    float4 v = *(const float4*)&V[e];
    *(uint2*)&g_vh[e] = make_uint2(pkh(v.x, v.y), pkh(v.z, v.w));
}

// cp.async [rows x 64] fp16 tile into stride-144 smem
__device__ __forceinline__ void cpa_tile64(uint32_t dstbase, const __half* src, int tid) {
    #pragma unroll
    for (int i = tid; i < 512; i += NTHR) {
        int r = i >> 3, c8 = i & 7;
        CPA16(dstbase + r * STRB + c8 * 16, src + (long)r * DD + c8 * 8);
    }
}
__device__ __forceinline__ void cpa_tile128(uint32_t dstbase, const __half* src, int tid) {
    #pragma unroll
    for (int i = tid; i < 1024; i += NTHR) {
        int r = i >> 3, c8 = i & 7;
        CPA16(dstbase + r * STRB + c8 * 16, src + (long)r * DD + c8 * 8);
    }
}

__global__ __launch_bounds__(NTHR, 2)
void fa_mma_kernel(const int* __restrict__ mask,
                   float* __restrict__ out_o, float* __restrict__ out_p)
{
    extern __shared__ char sm[];
    const uint32_t sb = s2u(sm);
    const int tid = threadIdx.x, wid = tid >> 5, lane = tid & 31;
    const int qg = wid & 3, cg = wid >> 2;
    const int q0 = qg * 16;

    const int qtile = blockIdx.x, h = blockIdx.y, b = blockIdx.z;
    const long bh = (long)(b * HH + h);
    const long qbase = bh * SS + (long)qtile * QB;
    const long kvbase = bh * SS;

    // ---- prologue: Q tile + mask + A chunk 0 (128-row KH) ----
    cpa_tile64(sb + OFF_QH, g_qh + qbase * DD, tid);
    #pragma unroll
    for (int i = tid; i < 512; i += NTHR)
        CPA16(sb + OFF_MSKF + i * 16, mask + (long)b * SS + i * 4);
    cpa_tile128(sb + STA_OFF(0), g_kh + kvbase * DD, tid);
    CPA_COMMIT();

    // per-lane ldmatrix addresses
    const uint32_t aoff = (uint32_t)(q0 + (lane & 15)) * STRB + ((lane >> 4) & 1) * 16;
    const uint32_t koffA = (uint32_t)(cg * 64 + (lane & 7) + ((lane & 16) ? 8 : 0)) * STRB
                         + ((lane & 8) ? 16 : 0);
    const uint32_t koffB = (uint32_t)(cg * 32 + (lane & 7) + ((lane & 16) ? 8 : 0)) * STRB
                         + ((lane & 8) ? 16 : 0);
    const uint32_t voff = (uint32_t)(cg * 32 + (lane & 15)) * STRB + ((lane >> 4) & 1) * 16;

    float*   fbf = (float*)(sm + OFF_MSKF);
    __half2* fbh = (__half2*)(sm + OFF_MSKH);

    CPA_WAIT0();
    __syncthreads();

    // mask ints -> float bias (in place) + half2 bias
    {
        int* mi = (int*)(sm + OFF_MSKF);
        for (int i = tid; i < SS / 2; i += NTHR) {
            int2 m = *(const int2*)&mi[2 * i];
            float b0 = m.x ? 0.0f : -1e30f;
            float b1 = m.y ? 0.0f : -1e30f;
            fbh[i] = __floats2half2_rn(b0, b1);
            fbf[2 * i] = b0; fbf[2 * i + 1] = b1;
        }
    }
    // hoist Q fragments (m16 x k64 = 16 regs)
    uint32_t aHq[4][4];
    #pragma unroll
    for (int s = 0; s < 4; s++)
        ldsm4(aHq[s], sb + OFF_QH + aoff + s * 32);
    __syncthreads();   // biases visible to all

    // ===== Pass A: 1-term fp16 scores, f16 accumulators -> row sums =====
    float rs0 = 0.0f, rs1 = 0.0f;
    for (int ch = 0; ch < NCHA; ch++) {
        const int st = ch & 1;
        if (ch > 0) { CPA_WAIT0(); __syncthreads(); }
        if (ch + 1 < NCHA) {
            cpa_tile128(sb + STA_OFF(st ^ 1),
                        g_kh + (kvbase + (long)(ch + 1) * NCA) * DD, tid);
            CPA_COMMIT();
        }

        uint32_t hacc[8][2];
        #pragma unroll
        for (int j = 0; j < 8; j++) { hacc[j][0] = 0u; hacc[j][1] = 0u; }
        #pragma unroll
        for (int s = 0; s < 4; s++) {
            #pragma unroll
            for (int jp = 0; jp < 4; jp++) {
                uint32_t bH[4];
                ldsm4(bH, sb + STA_OFF(st) + koffA + jp * (16 * STRB) + s * 32);
                mmah16(hacc[2 * jp],     aHq[s], bH[0], bH[1]);
                mmah16(hacc[2 * jp + 1], aHq[s], bH[2], bH[3]);
            }
        }
        __half2 hs0 = __floats2half2_rn(0.f, 0.f), hs1 = hs0;
        #pragma unroll
        for (int jt = 0; jt < 8; jt++) {
            int colb = ch * NCA + cg * 64 + 8 * jt + 2 * (lane & 3);
            __half2 fb = fbh[colb >> 1];
            hs0 = __hadd2(hs0, h2ex2(__hadd2(*(__half2*)&hacc[jt][0], fb)));
            hs1 = __hadd2(hs1, h2ex2(__hadd2(*(__half2*)&hacc[jt][1], fb)));
        }
        rs0 += __low2float(hs0) + __high2float(hs0);
        rs1 += __low2float(hs1) + __high2float(hs1);
    }

    __syncthreads();   // all warps done with A stages

    // prefetch pass-B chunk 0 (KH, VH) — overlaps rowsum reduction
    cpa_tile64(sb + STB_OFF(0, 0), g_kh + kvbase * DD, tid);
    cpa_tile64(sb + STB_OFF(0, 1), g_vh + kvbase * DD, tid);
    CPA_COMMIT();

    // ---- row sums: quad-lane reduce, cross-half via smem ----
    rs0 += __shfl_xor_sync(0xffffffffu, rs0, 1);
    rs0 += __shfl_xor_sync(0xffffffffu, rs0, 2);
    rs1 += __shfl_xor_sync(0xffffffffu, rs1, 1);
    rs1 += __shfl_xor_sync(0xffffffffu, rs1, 2);
    float* l2p = (float*)(sm + OFF_L2);
    if ((lane & 3) == 0) {
        l2p[2 * (q0 + (lane >> 2)) + cg]     = rs0;
        l2p[2 * (q0 + 8 + (lane >> 2)) + cg] = rs1;
    }
    __syncthreads();
    const float il0 = 1.0f / (l2p[2 * (q0 + (lane >> 2))] + l2p[2 * (q0 + (lane >> 2)) + 1]);
    const float il1 = 1.0f / (l2p[2 * (q0 + 8 + (lane >> 2))] + l2p[2 * (q0 + 8 + (lane >> 2)) + 1]);
    const long row0 = qbase + q0 + (lane >> 2);

    float oacc[8][4];
    #pragma unroll
    for (int j = 0; j < 8; j++)
        #pragma unroll
        for (int i = 0; i < 4; i++) oacc[j][i] = 0.0f;

    // ===== Pass B: 1-term S (fp32 accum) -> fp32 exp -> probs out + PV =====
    for (int ch = 0; ch < NCHB; ch++) {
        const int st = ch & 1;
        CPA_WAIT0();
        __syncthreads();
        if (ch + 1 < NCHB) {
            const long nb = (kvbase + (long)(ch + 1) * NCB) * DD;
            const int ns = st ^ 1;
            cpa_tile64(sb + STB_OFF(ns, 0), g_kh + nb, tid);
            cpa_tile64(sb + STB_OFF(ns, 1), g_vh + nb, tid);
            CPA_COMMIT();
        }

        // 1-term S over warp's n32
        float acc[4][4];
        #pragma unroll
        for (int j = 0; j < 4; j++)
            #pragma unroll
            for (int i = 0; i < 4; i++) acc[j][i] = 0.0f;
        #pragma unroll
        for (int s = 0; s < 4; s++) {
            #pragma unroll
            for (int jp = 0; jp < 2; jp++) {
                uint32_t bH[4];
                ldsm4(bH, sb + STB_OFF(st, 0) + koffB + jp * (16 * STRB) + s * 32);
                mmah(acc[2 * jp],     aHq[s], bH[0], bH[1]);
                mmah(acc[2 * jp + 1], aHq[s], bH[2], bH[3]);
            }
        }

        const uint32_t vh = sb + STB_OFF(st, 1) + voff;
        #pragma unroll
        for (int s2 = 0; s2 < 2; s2++) {
            uint32_t PH[4];
            #pragma unroll
            for (int hf = 0; hf < 2; hf++) {
                const int jt = 2 * s2 + hf;
                int colb = ch * NCB + cg * 32 + 8 * jt + 2 * (lane & 3);
                float2 fb = *(const float2*)&fbf[colb];
                float e0 = ex2f(acc[jt][0] + fb.x);
                float e1 = ex2f(acc[jt][1] + fb.y);
                float e2 = ex2f(acc[jt][2] + fb.x);
                float e3 = ex2f(acc[jt][3] + fb.y);
                // normalized probs out (fire-and-forget STG)
                *(float2*)&out_p[row0 * SS + colb]       = make_float2(e0 * il0, e1 * il0);
                *(float2*)&out_p[(row0 + 8) * SS + colb] = make_float2(e2 * il1, e3 * il1);
                PH[2 * hf]     = pkh(e0, e1);
                PH[2 * hf + 1] = pkh(e2, e3);
            }
            #pragma unroll
            for (int dp = 0; dp < 4; dp++) {
                uint32_t vH[4];
                ldsm4t(vH, vh + s2 * (16 * STRB) + dp * 32);
                mmah(oacc[2 * dp],     PH, vH[0], vH[1]);
                mmah(oacc[2 * dp + 1], PH, vH[2], vH[3]);
            }
        }
    }

    __syncthreads();   // all pass-B compute done (stage region free for staging)

    // ---- O cross-half reduction, normalize at write ----
    float* stg = (float*)(sm + OFF_OST);
    const int rlo = q0 + (lane >> 2), rhi = rlo + 8;
    if (cg == 1) {
        #pragma unroll
        for (int nt = 0; nt < 8; nt++) {
            int c = 8 * nt + 2 * (lane & 3);
            *(float2*)&stg[rlo * 64 + c] = make_float2(oacc[nt][0], oacc[nt][1]);
            *(float2*)&stg[rhi * 64 + c] = make_float2(oacc[nt][2], oacc[nt][3]);
        }
    }
    __syncthreads();
    if (cg == 0) {
        #pragma unroll
        for (int nt = 0; nt < 8; nt++) {
            int c = 8 * nt + 2 * (lane & 3);
            float2 s0 = *(const float2*)&stg[rlo * 64 + c];
            float2 s1 = *(const float2*)&stg[rhi * 64 + c];
            *(float2*)&out_o[row0 * DD + c] =
                make_float2((oacc[nt][0] + s0.x) * il0, (oacc[nt][1] + s0.y) * il0);
            *(float2*)&out_o[(row0 + 8) * DD + c] =
                make_float2((oacc[nt][2] + s1.x) * il1, (oacc[nt][3] + s1.y) * il1);
        }
    }
}

extern "C" void kernel_launch(void* const* d_in, const int* in_sizes, int n_in,
                              void* d_out, int out_size)
{
    const float* Q    = (const float*)d_in[0];
    const float* K    = (const float*)d_in[1];
    const float* V    = (const float*)d_in[2];
    const int*   mask = (const int*)d_in[3];

    float* out_o = (float*)d_out;                       // [B,H,S,D]
    float* out_p = out_o + (size_t)BB * HH * SS * DD;   // [B,H,S,S]

    convert_kernel<<<NELEM / 4 / 256, 256>>>(Q, K, V);

    cudaFuncSetAttribute(fa_mma_kernel,
                         cudaFuncAttributeMaxDynamicSharedMemorySize, SMEM_TOTAL);
    dim3 grid(SS / QB, HH, BB);   // (32, 16, 2) = 1024 CTAs, 2 per SM
    fa_mma_kernel<<<grid, NTHR, SMEM_TOTAL>>>(mask, out_o, out_p);
}

// round 16
// speedup vs baseline: 1.1283x; 1.0012x over previous
#include <cuda_runtime.h>
#include <cuda_fp16.h>
#include <stdint.h>

// ScaledDotProductAttention: B=2, H=16, S=2048, D=64, scale=8
#define BB 2
#define HH 16
#define SS 2048
#define DD 64
#define QB 64              // q rows per CTA
#define NCB 64             // k cols per B chunk
#define NCHB (SS / NCB)    // 32
#define NCA 128            // k cols per A chunk
#define NCHA (SS / NCA)    // 16
#define NTHR 128           // 4 warps: 2 q-groups (m32) x 2 col-halves
#define NELEM (BB * HH * SS * DD)

#define STRB 144                 // smem row stride bytes (ldmatrix conflict-free)
#define TILE64 (64 * STRB)       // 9216

#define OFF_QH 0
#define OFF_STAGE TILE64
// B stages: st{0,1} x {KH,VH}. A stages: st*2*TILE64 (128-row KH each).
#define STB_OFF(st, t) (OFF_STAGE + ((st) * 2 + (t)) * TILE64)
#define STA_OFF(st)    (OFF_STAGE + (st) * 2 * TILE64)
#define OFF_OST OFF_STAGE                     // O fp32 stage (16KB) overlays stages
#define OFF_MSKF (OFF_STAGE + 4 * TILE64)     // float bias[2048] (ints staged here)
#define OFF_MSKH (OFF_MSKF + SS * 4)          // half2 bias[1024]
#define OFF_L2   (OFF_MSKH + SS * 2)          // float[64][2]
#define SMEM_TOTAL (OFF_L2 + 64 * 2 * 4)      // 58880 B -> 2 CTAs/SM

// pre-converted fp16 tensors (Q pre-scaled by log2(e)/8); all single-term
__device__ __half g_qh[NELEM];
__device__ __half g_kh[NELEM];
__device__ __half g_vh[NELEM];

__device__ __forceinline__ uint32_t s2u(const void* p) {
    uint32_t a;
    asm("{ .reg .u64 t; cvta.to.shared.u64 t, %1; cvt.u32.u64 %0, t; }" : "=r"(a) : "l"(p));
    return a;
}
__device__ __forceinline__ void ldsm4(uint32_t r[4], uint32_t a) {
    asm volatile("ldmatrix.sync.aligned.m8n8.x4.shared.b16 {%0,%1,%2,%3}, [%4];"
                 : "=r"(r[0]), "=r"(r[1]), "=r"(r[2]), "=r"(r[3]) : "r"(a));
}
__device__ __forceinline__ void ldsm4t(uint32_t r[4], uint32_t a) {
    asm volatile("ldmatrix.sync.aligned.m8n8.x4.trans.shared.b16 {%0,%1,%2,%3}, [%4];"
                 : "=r"(r[0]), "=r"(r[1]), "=r"(r[2]), "=r"(r[3]) : "r"(a));
}
__device__ __forceinline__ void mmah(float c[4], const uint32_t a[4], uint32_t b0, uint32_t b1) {
    asm volatile("mma.sync.aligned.m16n8k16.row.col.f32.f16.f16.f32 "
                 "{%0,%1,%2,%3}, {%4,%5,%6,%7}, {%8,%9}, {%0,%1,%2,%3};"
                 : "+f"(c[0]), "+f"(c[1]), "+f"(c[2]), "+f"(c[3])
                 : "r"(a[0]), "r"(a[1]), "r"(a[2]), "r"(a[3]), "r"(b0), "r"(b1));
}
// f16-accumulator mma
__device__ __forceinline__ void mmah16(uint32_t c[2], const uint32_t a[4], uint32_t b0, uint32_t b1) {
    asm volatile("mma.sync.aligned.m16n8k16.row.col.f16.f16.f16.f16 "
                 "{%0,%1}, {%2,%3,%4,%5}, {%6,%7}, {%0,%1};"
                 : "+r"(c[0]), "+r"(c[1])
                 : "r"(a[0]), "r"(a[1]), "r"(a[2]), "r"(a[3]), "r"(b0), "r"(b1));
}
__device__ __forceinline__ uint32_t pkh(float a, float b) {
    __half2 t = __floats2half2_rn(a, b);
    return *(uint32_t*)&t;
}
__device__ __forceinline__ float ex2f(float x) {
    float r;
    asm("ex2.approx.f32 %0, %1;" : "=f"(r) : "f"(x));
    return r;
}
__device__ __forceinline__ __half2 h2ex2(__half2 x) {
    uint32_t xi = *(uint32_t*)&x, r;
    asm("ex2.approx.f16x2 %0, %1;" : "=r"(r) : "r"(xi));
    return *(__half2*)&r;
}
#define CPA16(dst, src) \
    asm volatile("cp.async.cg.shared.global [%0], [%1], 16;" :: "r"(dst), "l"(src) : "memory")
#define CPA_COMMIT() asm volatile("cp.async.commit_group;" ::: "memory")
#define CPA_WAIT0()  asm volatile("cp.async.wait_group 0;" ::: "memory")

// ---- pre-pass: Q (scaled), K, V -> fp16 ----
__global__ void convert_kernel(const float* __restrict__ Q, const float* __restrict__ K,
                               const float* __restrict__ V)
{
    long i = (long)blockIdx.x * blockDim.x + threadIdx.x;
    if (i >= NELEM / 4) return;
    long e = i * 4;
    const float QSC = 0.125f * 1.4426950408889634f;   // (1/8)*log2(e): exp -> exp2
    float4 q = *(const float4*)&Q[e];
    *(uint2*)&g_qh[e] = make_uint2(pkh(q.x * QSC, q.y * QSC), pkh(q.z * QSC, q.w * QSC));
    float4 k = *(const float4*)&K[e];
    *(uint2*)&g_kh[e] = make_uint2(pkh(k.x, k.y), pkh(k.z, k.w));
    float4 v = *(const float4*)&V[e];
    *(uint2*)&g_vh[e] = make_uint2(pkh(v.x, v.y), pkh(v.z, v.w));
}

// cp.async [rows x 64] fp16 tile into stride-144 smem
__device__ __forceinline__ void cpa_tile64(uint32_t dstbase, const __half* src, int tid) {
    #pragma unroll
    for (int i = tid; i < 512; i += NTHR) {
        int r = i >> 3, c8 = i & 7;
        CPA16(dstbase + r * STRB + c8 * 16, src + (long)r * DD + c8 * 8);
    }
}
__device__ __forceinline__ void cpa_tile128(uint32_t dstbase, const __half* src, int tid) {
    #pragma unroll
    for (int i = tid; i < 1024; i += NTHR) {
        int r = i >> 3, c8 = i & 7;
        CPA16(dstbase + r * STRB + c8 * 16, src + (long)r * DD + c8 * 8);
    }
}

__global__ __launch_bounds__(NTHR, 2)
void fa_mma_kernel(const int* __restrict__ mask,
                   float* __restrict__ out_o, float* __restrict__ out_p)
{
    extern __shared__ char sm[];
    const uint32_t sb = s2u(sm);
    const int tid = threadIdx.x, wid = tid >> 5, lane = tid & 31;
    const int qg = wid >> 1, cg = wid & 1;
    const int q0 = qg * 32;

    const int qtile = blockIdx.x, h = blockIdx.y, b = blockIdx.z;
    const long bh = (long)(b * HH + h);
    const long qbase = bh * SS + (long)qtile * QB;
    const long kvbase = bh * SS;

    // ---- prologue: Q tile + mask + A chunk 0 (128-row KH) ----
    cpa_tile64(sb + OFF_QH, g_qh + qbase * DD, tid);
    #pragma unroll
    for (int i = tid; i < 512; i += NTHR)
        CPA16(sb + OFF_MSKF + i * 16, mask + (long)b * SS + i * 4);
    cpa_tile128(sb + STA_OFF(0), g_kh + kvbase * DD, tid);
    CPA_COMMIT();

    // per-lane ldmatrix addresses
    const uint32_t aoff = (uint32_t)(q0 + (lane & 15)) * STRB + ((lane >> 4) & 1) * 16;
    const uint32_t koffA = (uint32_t)(cg * 64 + (lane & 7) + ((lane & 16) ? 8 : 0)) * STRB
                         + ((lane & 8) ? 16 : 0);
    const uint32_t koffB = (uint32_t)(cg * 32 + (lane & 7) + ((lane & 16) ? 8 : 0)) * STRB
                         + ((lane & 8) ? 16 : 0);
    const uint32_t voff = (uint32_t)(cg * 32 + (lane & 15)) * STRB + ((lane >> 4) & 1) * 16;

    float*   fbf = (float*)(sm + OFF_MSKF);
    __half2* fbh = (__half2*)(sm + OFF_MSKH);

    CPA_WAIT0();
    __syncthreads();

    // mask ints -> float bias (in place) + half2 bias
    {
        int* mi = (int*)(sm + OFF_MSKF);
        for (int i = tid; i < SS / 2; i += NTHR) {
            int2 m = *(const int2*)&mi[2 * i];
            float b0 = m.x ? 0.0f : -1e30f;
            float b1 = m.y ? 0.0f : -1e30f;
            fbh[i] = __floats2half2_rn(b0, b1);
            fbf[2 * i] = b0; fbf[2 * i + 1] = b1;
        }
    }
    // hoist Q fragments (m32 x k64 = 32 regs)
    uint32_t aHq[2][4][4];
    #pragma unroll
    for (int t = 0; t < 2; t++)
        #pragma unroll
        for (int s = 0; s < 4; s++)
            ldsm4(aHq[t][s], sb + OFF_QH + aoff + t * (16 * STRB) + s * 32);
    __syncthreads();   // biases visible to all

    // ===== Pass A: 1-term fp16 scores, f16 accumulators -> row sums =====
    float rs[2][2] = {{0.f, 0.f}, {0.f, 0.f}};
    for (int ch = 0; ch < NCHA; ch++) {
        const int st = ch & 1;
        if (ch > 0) { CPA_WAIT0(); __syncthreads(); }
        if (ch + 1 < NCHA) {
            cpa_tile128(sb + STA_OFF(st ^ 1),
                        g_kh + (kvbase + (long)(ch + 1) * NCA) * DD, tid);
            CPA_COMMIT();
        }

        uint32_t hacc[2][8][2];
        #pragma unroll
        for (int t = 0; t < 2; t++)
            #pragma unroll
            for (int j = 0; j < 8; j++) { hacc[t][j][0] = 0u; hacc[t][j][1] = 0u; }
        #pragma unroll
        for (int s = 0; s < 4; s++) {
            #pragma unroll
            for (int jp = 0; jp < 4; jp++) {
                uint32_t bH[4];
                ldsm4(bH, sb + STA_OFF(st) + koffA + jp * (16 * STRB) + s * 32);
                #pragma unroll
                for (int t = 0; t < 2; t++) {
                    mmah16(hacc[t][2 * jp],     aHq[t][s], bH[0], bH[1]);
                    mmah16(hacc[t][2 * jp + 1], aHq[t][s], bH[2], bH[3]);
                }
            }
        }
        #pragma unroll
        for (int t = 0; t < 2; t++) {
            __half2 hs0 = __floats2half2_rn(0.f, 0.f), hs1 = hs0;
            #pragma unroll
            for (int jt = 0; jt < 8; jt++) {
                int colb = ch * NCA + cg * 64 + 8 * jt + 2 * (lane & 3);
                __half2 fb = fbh[colb >> 1];
                hs0 = __hadd2(hs0, h2ex2(__hadd2(*(__half2*)&hacc[t][jt][0], fb)));
                hs1 = __hadd2(hs1, h2ex2(__hadd2(*(__half2*)&hacc[t][jt][1], fb)));
            }
            rs[t][0] += __low2float(hs0) + __high2float(hs0);
            rs[t][1] += __low2float(hs1) + __high2float(hs1);
        }
    }

    __syncthreads();   // all warps done with A stages

    // prefetch pass-B chunk 0 (KH, VH) — overlaps rowsum reduction
    cpa_tile64(sb + STB_OFF(0, 0), g_kh + kvbase * DD, tid);
    cpa_tile64(sb + STB_OFF(0, 1), g_vh + kvbase * DD, tid);
    CPA_COMMIT();

    // ---- row sums: quad-lane reduce, cross-half via smem ----
    #pragma unroll
    for (int t = 0; t < 2; t++)
        #pragma unroll
        for (int i = 0; i < 2; i++) {
            rs[t][i] += __shfl_xor_sync(0xffffffffu, rs[t][i], 1);
            rs[t][i] += __shfl_xor_sync(0xffffffffu, rs[t][i], 2);
        }
    float* l2p = (float*)(sm + OFF_L2);
    if ((lane & 3) == 0) {
        #pragma unroll
        for (int t = 0; t < 2; t++) {
            l2p[2 * (q0 + t * 16 + (lane >> 2)) + cg]     = rs[t][0];
            l2p[2 * (q0 + t * 16 + 8 + (lane >> 2)) + cg] = rs[t][1];
        }
    }
    __syncthreads();
    float ilv[2][2];
    #pragma unroll
    for (int t = 0; t < 2; t++) {
        int row = q0 + t * 16 + (lane >> 2);
        ilv[t][0] = 1.0f / (l2p[2 * row] + l2p[2 * row + 1]);
        ilv[t][1] = 1.0f / (l2p[2 * (row + 8)] + l2p[2 * (row + 8) + 1]);
    }

    float oacc[2][8][4];
    #pragma unroll
    for (int t = 0; t < 2; t++)
        #pragma unroll
        for (int j = 0; j < 8; j++)
            #pragma unroll
            for (int i = 0; i < 4; i++) oacc[t][j][i] = 0.0f;

    // ===== Pass B: 1-term S (fp32 accum) -> fp32 exp -> probs out + PV =====
    for (int ch = 0; ch < NCHB; ch++) {
        const int st = ch & 1;
        CPA_WAIT0();
        __syncthreads();
        if (ch + 1 < NCHB) {
            const long nb = (kvbase + (long)(ch + 1) * NCB) * DD;
            const int ns = st ^ 1;
            cpa_tile64(sb + STB_OFF(ns, 0), g_kh + nb, tid);
            cpa_tile64(sb + STB_OFF(ns, 1), g_vh + nb, tid);
            CPA_COMMIT();
        }

        // 1-term S over warp's n32, both m16 tiles
        float acc[2][4][4];
        #pragma unroll
        for (int t = 0; t < 2; t++)
            #pragma unroll
            for (int j = 0; j < 4; j++)
                #pragma unroll
                for (int i = 0; i < 4; i++) acc[t][j][i] = 0.0f;
        #pragma unroll
        for (int s = 0; s < 4; s++) {
            #pragma unroll
            for (int jp = 0; jp < 2; jp++) {
                uint32_t bH[4];
                ldsm4(bH, sb + STB_OFF(st, 0) + koffB + jp * (16 * STRB) + s * 32);
                #pragma unroll
                for (int t = 0; t < 2; t++) {
                    mmah(acc[t][2 * jp],     aHq[t][s], bH[0], bH[1]);
                    mmah(acc[t][2 * jp + 1], aHq[t][s], bH[2], bH[3]);
                }
            }
        }

        const uint32_t vh = sb + STB_OFF(st, 1) + voff;
        #pragma unroll
        for (int s2 = 0; s2 < 2; s2++) {
            uint32_t PH[2][4];
            #pragma unroll
            for (int t = 0; t < 2; t++) {
                const long row0t = qbase + q0 + t * 16 + (lane >> 2);
                #pragma unroll
                for (int hf = 0; hf < 2; hf++) {
                    const int jt = 2 * s2 + hf;
                    int colb = ch * NCB + cg * 32 + 8 * jt + 2 * (lane & 3);
                    float2 fb = *(const float2*)&fbf[colb];
                    float e0 = ex2f(acc[t][jt][0] + fb.x);
                    float e1 = ex2f(acc[t][jt][1] + fb.y);
                    float e2 = ex2f(acc[t][jt][2] + fb.x);
                    float e3 = ex2f(acc[t][jt][3] + fb.y);
                    *(float2*)&out_p[row0t * SS + colb] =
                        make_float2(e0 * ilv[t][0], e1 * ilv[t][0]);
                    *(float2*)&out_p[(row0t + 8) * SS + colb] =
                        make_float2(e2 * ilv[t][1], e3 * ilv[t][1]);
                    PH[t][2 * hf]     = pkh(e0, e1);
                    PH[t][2 * hf + 1] = pkh(e2, e3);
                }
            }
            #pragma unroll
            for (int dp = 0; dp < 4; dp++) {
                uint32_t vH[4];
                ldsm4t(vH, vh + s2 * (16 * STRB) + dp * 32);
                #pragma unroll
                for (int t = 0; t < 2; t++) {
                    mmah(oacc[t][2 * dp],     PH[t], vH[0], vH[1]);
                    mmah(oacc[t][2 * dp + 1], PH[t], vH[2], vH[3]);
                }
            }
        }
    }

    __syncthreads();   // all pass-B compute done (stage region free for staging)

    // ---- O cross-half reduction, normalize at write ----
    float* stg = (float*)(sm + OFF_OST);
    if (cg == 1) {
        #pragma unroll
        for (int t = 0; t < 2; t++) {
            const int rlo = q0 + t * 16 + (lane >> 2);
            #pragma unroll
            for (int nt = 0; nt < 8; nt++) {
                int c = 8 * nt + 2 * (lane & 3);
                *(float2*)&stg[rlo * 64 + c] = make_float2(oacc[t][nt][0], oacc[t][nt][1]);
                *(float2*)&stg[(rlo + 8) * 64 + c] = make_float2(oacc[t][nt][2], oacc[t][nt][3]);
            }
        }
    }
    __syncthreads();
    if (cg == 0) {
        #pragma unroll
        for (int t = 0; t < 2; t++) {
            const int rlo = q0 + t * 16 + (lane >> 2);
            const long row0t = qbase + rlo;
            #pragma unroll
            for (int nt = 0; nt < 8; nt++) {
                int c = 8 * nt + 2 * (lane & 3);
                float2 s0 = *(const float2*)&stg[rlo * 64 + c];
                float2 s1 = *(const float2*)&stg[(rlo + 8) * 64 + c];
                *(float2*)&out_o[row0t * DD + c] =
                    make_float2((oacc[t][nt][0] + s0.x) * ilv[t][0],
                                (oacc[t][nt][1] + s0.y) * ilv[t][0]);
                *(float2*)&out_o[(row0t + 8) * DD + c] =
                    make_float2((oacc[t][nt][2] + s1.x) * ilv[t][1],
                                (oacc[t][nt][3] + s1.y) * ilv[t][1]);
            }
        }
    }
}

extern "C" void kernel_launch(void* const* d_in, const int* in_sizes, int n_in,
                              void* d_out, int out_size)
{
    const float* Q    = (const float*)d_in[0];
    const float* K    = (const float*)d_in[1];
    const float* V    = (const float*)d_in[2];
    const int*   mask = (const int*)d_in[3];

    float* out_o = (float*)d_out;                       // [B,H,S,D]
    float* out_p = out_o + (size_t)BB * HH * SS * DD;   // [B,H,S,S]

    convert_kernel<<<NELEM / 4 / 256, 256>>>(Q, K, V);

    cudaFuncSetAttribute(fa_mma_kernel,
                         cudaFuncAttributeMaxDynamicSharedMemorySize, SMEM_TOTAL);
    dim3 grid(SS / QB, HH, BB);   // (32, 16, 2) = 1024 CTAs, 2 per SM
    fa_mma_kernel<<<grid, NTHR, SMEM_TOTAL>>>(mask, out_o, out_p);
}

// round 17
// speedup vs baseline: 1.1997x; 1.0633x over previous
#include <cuda_runtime.h>
#include <cuda_fp16.h>
#include <stdint.h>

// ScaledDotProductAttention: B=2, H=16, S=2048, D=64, scale=8
#define BB 2
#define HH 16
#define SS 2048
#define DD 64
#define QB 64              // q rows per CTA
#define NCB 64             // k cols per B chunk
#define NCHB (SS / NCB)    // 32
#define NCA 128            // k cols per A chunk
#define NCHA (SS / NCA)    // 16
#define NTHR 128           // 4 warps: 2 q-groups (m32) x 2 col-halves
#define NELEM (BB * HH * SS * DD)

#define STRB 144                 // smem row stride bytes (ldmatrix conflict-free)
#define TILE64 (64 * STRB)       // 9216

#define OFF_QH 0
#define OFF_STAGE TILE64
// B stages: st{0,1} x {KH,VH}. A stages: st*2*TILE64 (128-row KH each).
#define STB_OFF(st, t) (OFF_STAGE + ((st) * 2 + (t)) * TILE64)
#define STA_OFF(st)    (OFF_STAGE + (st) * 2 * TILE64)
#define OFF_OST OFF_STAGE                     // O fp32 stage (16KB) overlays stages
#define OFF_MSKF (OFF_STAGE + 4 * TILE64)     // float bias[2048] (ints staged here)
#define OFF_MSKH (OFF_MSKF + SS * 4)          // half2 bias[1024]
#define OFF_L2   (OFF_MSKH + SS * 2)          // float[64][2]
#define SMEM_TOTAL (OFF_L2 + 64 * 2 * 4)      // 58880 B -> 3 CTAs/SM

// pre-converted fp16 tensors (Q pre-scaled by log2(e)/8); all single-term
__device__ __half g_qh[NELEM];
__device__ __half g_kh[NELEM];
__device__ __half g_vh[NELEM];

__device__ __forceinline__ uint32_t s2u(const void* p) {
    uint32_t a;
    asm("{ .reg .u64 t; cvta.to.shared.u64 t, %1; cvt.u32.u64 %0, t; }" : "=r"(a) : "l"(p));
    return a;
}
__device__ __forceinline__ void ldsm4(uint32_t r[4], uint32_t a) {
    asm volatile("ldmatrix.sync.aligned.m8n8.x4.shared.b16 {%0,%1,%2,%3}, [%4];"
                 : "=r"(r[0]), "=r"(r[1]), "=r"(r[2]), "=r"(r[3]) : "r"(a));
}
__device__ __forceinline__ void ldsm4t(uint32_t r[4], uint32_t a) {
    asm volatile("ldmatrix.sync.aligned.m8n8.x4.trans.shared.b16 {%0,%1,%2,%3}, [%4];"
                 : "=r"(r[0]), "=r"(r[1]), "=r"(r[2]), "=r"(r[3]) : "r"(a));
}
__device__ __forceinline__ void mmah(float c[4], const uint32_t a[4], uint32_t b0, uint32_t b1) {
    asm volatile("mma.sync.aligned.m16n8k16.row.col.f32.f16.f16.f32 "
                 "{%0,%1,%2,%3}, {%4,%5,%6,%7}, {%8,%9}, {%0,%1,%2,%3};"
                 : "+f"(c[0]), "+f"(c[1]), "+f"(c[2]), "+f"(c[3])
                 : "r"(a[0]), "r"(a[1]), "r"(a[2]), "r"(a[3]), "r"(b0), "r"(b1));
}
// f16-accumulator mma
__device__ __forceinline__ void mmah16(uint32_t c[2], const uint32_t a[4], uint32_t b0, uint32_t b1) {
    asm volatile("mma.sync.aligned.m16n8k16.row.col.f16.f16.f16.f16 "
                 "{%0,%1}, {%2,%3,%4,%5}, {%6,%7}, {%0,%1};"
                 : "+r"(c[0]), "+r"(c[1])
                 : "r"(a[0]), "r"(a[1]), "r"(a[2]), "r"(a[3]), "r"(b0), "r"(b1));
}
__device__ __forceinline__ uint32_t pkh(float a, float b) {
    __half2 t = __floats2half2_rn(a, b);
    return *(uint32_t*)&t;
}
__device__ __forceinline__ float ex2f(float x) {
    float r;
    asm("ex2.approx.f32 %0, %1;" : "=f"(r) : "f"(x));
    return r;
}
__device__ __forceinline__ __half2 h2ex2(__half2 x) {
    uint32_t xi = *(uint32_t*)&x, r;
    asm("ex2.approx.f16x2 %0, %1;" : "=r"(r) : "r"(xi));
    return *(__half2*)&r;
}
#define CPA16(dst, src) \
    asm volatile("cp.async.cg.shared.global [%0], [%1], 16;" :: "r"(dst), "l"(src) : "memory")
#define CPA_COMMIT() asm volatile("cp.async.commit_group;" ::: "memory")
#define CPA_WAIT0()  asm volatile("cp.async.wait_group 0;" ::: "memory")

// ---- pre-pass: Q (scaled), K, V -> fp16 ----
__global__ void convert_kernel(const float* __restrict__ Q, const float* __restrict__ K,
                               const float* __restrict__ V)
{
    long i = (long)blockIdx.x * blockDim.x + threadIdx.x;
    if (i >= NELEM / 4) return;
    long e = i * 4;
    const float QSC = 0.125f * 1.4426950408889634f;   // (1/8)*log2(e): exp -> exp2
    float4 q = *(const float4*)&Q[e];
    *(uint2*)&g_qh[e] = make_uint2(pkh(q.x * QSC, q.y * QSC), pkh(q.z * QSC, q.w * QSC));
    float4 k = *(const float4*)&K[e];
    *(uint2*)&g_kh[e] = make_uint2(pkh(k.x, k.y), pkh(k.z, k.w));
    float4 v = *(const float4*)&V[e];
    *(uint2*)&g_vh[e] = make_uint2(pkh(v.x, v.y), pkh(v.z, v.w));
}

// cp.async [rows x 64] fp16 tile into stride-144 smem
__device__ __forceinline__ void cpa_tile64(uint32_t dstbase, const __half* src, int tid) {
    #pragma unroll
    for (int i = tid; i < 512; i += NTHR) {
        int r = i >> 3, c8 = i & 7;
        CPA16(dstbase + r * STRB + c8 * 16, src + (long)r * DD + c8 * 8);
    }
}
__device__ __forceinline__ void cpa_tile128(uint32_t dstbase, const __half* src, int tid) {
    #pragma unroll
    for (int i = tid; i < 1024; i += NTHR) {
        int r = i >> 3, c8 = i & 7;
        CPA16(dstbase + r * STRB + c8 * 16, src + (long)r * DD + c8 * 8);
    }
}

__global__ __launch_bounds__(NTHR, 3)
void fa_mma_kernel(const int* __restrict__ mask,
                   float* __restrict__ out_o, float* __restrict__ out_p)
{
    extern __shared__ char sm[];
    const uint32_t sb = s2u(sm);
    const int tid = threadIdx.x, wid = tid >> 5, lane = tid & 31;
    const int qg = wid >> 1, cg = wid & 1;
    const int q0 = qg * 32;

    const int qtile = blockIdx.x, h = blockIdx.y, b = blockIdx.z;
    const long bh = (long)(b * HH + h);
    const long qbase = bh * SS + (long)qtile * QB;
    const long kvbase = bh * SS;

    // ---- prologue: Q tile + mask + A chunk 0 (128-row KH) ----
    cpa_tile64(sb + OFF_QH, g_qh + qbase * DD, tid);
    #pragma unroll
    for (int i = tid; i < 512; i += NTHR)
        CPA16(sb + OFF_MSKF + i * 16, mask + (long)b * SS + i * 4);
    cpa_tile128(sb + STA_OFF(0), g_kh + kvbase * DD, tid);
    CPA_COMMIT();

    // per-lane ldmatrix addresses
    const uint32_t aoff = (uint32_t)(q0 + (lane & 15)) * STRB + ((lane >> 4) & 1) * 16;
    const uint32_t koffA = (uint32_t)(cg * 64 + (lane & 7) + ((lane & 16) ? 8 : 0)) * STRB
                         + ((lane & 8) ? 16 : 0);
    const uint32_t koffB = (uint32_t)(cg * 32 + (lane & 7) + ((lane & 16) ? 8 : 0)) * STRB
                         + ((lane & 8) ? 16 : 0);
    const uint32_t voff = (uint32_t)(cg * 32 + (lane & 15)) * STRB + ((lane >> 4) & 1) * 16;

    float*   fbf = (float*)(sm + OFF_MSKF);
    __half2* fbh = (__half2*)(sm + OFF_MSKH);

    CPA_WAIT0();
    __syncthreads();

    // mask ints -> float bias (in place) + half2 bias
    {
        int* mi = (int*)(sm + OFF_MSKF);
        for (int i = tid; i < SS / 2; i += NTHR) {
            int2 m = *(const int2*)&mi[2 * i];
            float b0 = m.x ? 0.0f : -1e30f;
            float b1 = m.y ? 0.0f : -1e30f;
            fbh[i] = __floats2half2_rn(b0, b1);
            fbf[2 * i] = b0; fbf[2 * i + 1] = b1;
        }
    }
    __syncthreads();   // biases visible to all

    // ===== Pass A: 1-term fp16 scores, f16 accumulators -> row sums =====
    // Q frags reloaded per chunk from resident smem Q tile (saves 32 regs for occ=3)
    float rs[2][2] = {{0.f, 0.f}, {0.f, 0.f}};
    for (int ch = 0; ch < NCHA; ch++) {
        const int st = ch & 1;
        if (ch > 0) { CPA_WAIT0(); __syncthreads(); }
        if (ch + 1 < NCHA) {
            cpa_tile128(sb + STA_OFF(st ^ 1),
                        g_kh + (kvbase + (long)(ch + 1) * NCA) * DD, tid);
            CPA_COMMIT();
        }

        uint32_t hacc[2][8][2];
        #pragma unroll
        for (int t = 0; t < 2; t++)
            #pragma unroll
            for (int j = 0; j < 8; j++) { hacc[t][j][0] = 0u; hacc[t][j][1] = 0u; }
        #pragma unroll
        for (int s = 0; s < 4; s++) {
            uint32_t aq[2][4];
            ldsm4(aq[0], sb + OFF_QH + aoff + s * 32);
            ldsm4(aq[1], sb + OFF_QH + aoff + 16 * STRB + s * 32);
            #pragma unroll
            for (int jp = 0; jp < 4; jp++) {
                uint32_t bH[4];
                ldsm4(bH, sb + STA_OFF(st) + koffA + jp * (16 * STRB) + s * 32);
                #pragma unroll
                for (int t = 0; t < 2; t++) {
                    mmah16(hacc[t][2 * jp],     aq[t], bH[0], bH[1]);
                    mmah16(hacc[t][2 * jp + 1], aq[t], bH[2], bH[3]);
                }
            }
        }
        #pragma unroll
        for (int t = 0; t < 2; t++) {
            __half2 hs0 = __floats2half2_rn(0.f, 0.f), hs1 = hs0;
            #pragma unroll
            for (int jt = 0; jt < 8; jt++) {
                int colb = ch * NCA + cg * 64 + 8 * jt + 2 * (lane & 3);
                __half2 fb = fbh[colb >> 1];
                hs0 = __hadd2(hs0, h2ex2(__hadd2(*(__half2*)&hacc[t][jt][0], fb)));
                hs1 = __hadd2(hs1, h2ex2(__hadd2(*(__half2*)&hacc[t][jt][1], fb)));
            }
            rs[t][0] += __low2float(hs0) + __high2float(hs0);
            rs[t][1] += __low2float(hs1) + __high2float(hs1);
        }
    }

    __syncthreads();   // all warps done with A stages

    // prefetch pass-B chunk 0 (KH, VH) — overlaps rowsum reduction
    cpa_tile64(sb + STB_OFF(0, 0), g_kh + kvbase * DD, tid);
    cpa_tile64(sb + STB_OFF(0, 1), g_vh + kvbase * DD, tid);
    CPA_COMMIT();

    // ---- row sums: quad-lane reduce, cross-half via smem ----
    #pragma unroll
    for (int t = 0; t < 2; t++)
        #pragma unroll
        for (int i = 0; i < 2; i++) {
            rs[t][i] += __shfl_xor_sync(0xffffffffu, rs[t][i], 1);
            rs[t][i] += __shfl_xor_sync(0xffffffffu, rs[t][i], 2);
        }
    float* l2p = (float*)(sm + OFF_L2);
    if ((lane & 3) == 0) {
        #pragma unroll
        for (int t = 0; t < 2; t++) {
            l2p[2 * (q0 + t * 16 + (lane >> 2)) + cg]     = rs[t][0];
            l2p[2 * (q0 + t * 16 + 8 + (lane >> 2)) + cg] = rs[t][1];
        }
    }
    __syncthreads();
    float ilv[2][2];
    #pragma unroll
    for (int t = 0; t < 2; t++) {
        int row = q0 + t * 16 + (lane >> 2);
        ilv[t][0] = 1.0f / (l2p[2 * row] + l2p[2 * row + 1]);
        ilv[t][1] = 1.0f / (l2p[2 * (row + 8)] + l2p[2 * (row + 8) + 1]);
    }

    float oacc[2][8][4];
    #pragma unroll
    for (int t = 0; t < 2; t++)
        #pragma unroll
        for (int j = 0; j < 8; j++)
            #pragma unroll
            for (int i = 0; i < 4; i++) oacc[t][j][i] = 0.0f;

    // ===== Pass B: 1-term S (fp32 accum) -> fp32 exp -> probs out + PV =====
    for (int ch = 0; ch < NCHB; ch++) {
        const int st = ch & 1;
        CPA_WAIT0();
        __syncthreads();
        if (ch + 1 < NCHB) {
            const long nb = (kvbase + (long)(ch + 1) * NCB) * DD;
            const int ns = st ^ 1;
            cpa_tile64(sb + STB_OFF(ns, 0), g_kh + nb, tid);
            cpa_tile64(sb + STB_OFF(ns, 1), g_vh + nb, tid);
            CPA_COMMIT();
        }

        // 1-term S over warp's n32, both m16 tiles (Q reloaded from smem)
        float acc[2][4][4];
        #pragma unroll
        for (int t = 0; t < 2; t++)
            #pragma unroll
            for (int j = 0; j < 4; j++)
                #pragma unroll
                for (int i = 0; i < 4; i++) acc[t][j][i] = 0.0f;
        #pragma unroll
        for (int s = 0; s < 4; s++) {
            uint32_t aq[2][4];
            ldsm4(aq[0], sb + OFF_QH + aoff + s * 32);
            ldsm4(aq[1], sb + OFF_QH + aoff + 16 * STRB + s * 32);
            #pragma unroll
            for (int jp = 0; jp < 2; jp++) {
                uint32_t bH[4];
                ldsm4(bH, sb + STB_OFF(st, 0) + koffB + jp * (16 * STRB) + s * 32);
                #pragma unroll
                for (int t = 0; t < 2; t++) {
                    mmah(acc[t][2 * jp],     aq[t], bH[0], bH[1]);
                    mmah(acc[t][2 * jp + 1], aq[t], bH[2], bH[3]);
                }
            }
        }

        const uint32_t vh = sb + STB_OFF(st, 1) + voff;
        #pragma unroll
        for (int s2 = 0; s2 < 2; s2++) {
            uint32_t PH[2][4];
            #pragma unroll
            for (int t = 0; t < 2; t++) {
                const long row0t = qbase + q0 + t * 16 + (lane >> 2);
                #pragma unroll
                for (int hf = 0; hf < 2; hf++) {
                    const int jt = 2 * s2 + hf;
                    int colb = ch * NCB + cg * 32 + 8 * jt + 2 * (lane & 3);
                    float2 fb = *(const float2*)&fbf[colb];
                    float e0 = ex2f(acc[t][jt][0] + fb.x);
                    float e1 = ex2f(acc[t][jt][1] + fb.y);
                    float e2 = ex2f(acc[t][jt][2] + fb.x);
                    float e3 = ex2f(acc[t][jt][3] + fb.y);
                    *(float2*)&out_p[row0t * SS + colb] =
                        make_float2(e0 * ilv[t][0], e1 * ilv[t][0]);
                    *(float2*)&out_p[(row0t + 8) * SS + colb] =
                        make_float2(e2 * ilv[t][1], e3 * ilv[t][1]);
                    PH[t][2 * hf]     = pkh(e0, e1);
                    PH[t][2 * hf + 1] = pkh(e2, e3);
                }
            }
            #pragma unroll
            for (int dp = 0; dp < 4; dp++) {
                uint32_t vH[4];
                ldsm4t(vH, vh + s2 * (16 * STRB) + dp * 32);
                #pragma unroll
                for (int t = 0; t < 2; t++) {
                    mmah(oacc[t][2 * dp],     PH[t], vH[0], vH[1]);
                    mmah(oacc[t][2 * dp + 1], PH[t], vH[2], vH[3]);
                }
            }
        }
    }

    __syncthreads();   // all pass-B compute done (stage region free for staging)

    // ---- O cross-half reduction, normalize at write ----
    float* stg = (float*)(sm + OFF_OST);
    if (cg == 1) {
        #pragma unroll
        for (int t = 0; t < 2; t++) {
            const int rlo = q0 + t * 16 + (lane >> 2);
            #pragma unroll
            for (int nt = 0; nt < 8; nt++) {
                int c = 8 * nt + 2 * (lane & 3);
                *(float2*)&stg[rlo * 64 + c] = make_float2(oacc[t][nt][0], oacc[t][nt][1]);
                *(float2*)&stg[(rlo + 8) * 64 + c] = make_float2(oacc[t][nt][2], oacc[t][nt][3]);
            }
        }
    }
    __syncthreads();
    if (cg == 0) {
        #pragma unroll
        for (int t = 0; t < 2; t++) {
            const int rlo = q0 + t * 16 + (lane >> 2);
            const long row0t = qbase + rlo;
            #pragma unroll
            for (int nt = 0; nt < 8; nt++) {
                int c = 8 * nt + 2 * (lane & 3);
                float2 s0 = *(const float2*)&stg[rlo * 64 + c];
                float2 s1 = *(const float2*)&stg[(rlo + 8) * 64 + c];
                *(float2*)&out_o[row0t * DD + c] =
                    make_float2((oacc[t][nt][0] + s0.x) * ilv[t][0],
                                (oacc[t][nt][1] + s0.y) * ilv[t][0]);
                *(float2*)&out_o[(row0t + 8) * DD + c] =
                    make_float2((oacc[t][nt][2] + s1.x) * ilv[t][1],
                                (oacc[t][nt][3] + s1.y) * ilv[t][1]);
            }
        }
    }
}

extern "C" void kernel_launch(void* const* d_in, const int* in_sizes, int n_in,
                              void* d_out, int out_size)
{
    const float* Q    = (const float*)d_in[0];
    const float* K    = (const float*)d_in[1];
    const float* V    = (const float*)d_in[2];
    const int*   mask = (const int*)d_in[3];

    float* out_o = (float*)d_out;                       // [B,H,S,D]
    float* out_p = out_o + (size_t)BB * HH * SS * DD;   // [B,H,S,S]

    convert_kernel<<<NELEM / 4 / 256, 256>>>(Q, K, V);

    cudaFuncSetAttribute(fa_mma_kernel,
                         cudaFuncAttributeMaxDynamicSharedMemorySize, SMEM_TOTAL);
    dim3 grid(SS / QB, HH, BB);   // (32, 16, 2) = 1024 CTAs, 3 per SM
    fa_mma_kernel<<<grid, NTHR, SMEM_TOTAL>>>(mask, out_o, out_p);
}